// round 14
// baseline (speedup 1.0000x reference)
#include <cuda_runtime.h>

// CTC forward loss — forward/backward split (two 512-step chains) with
// f32x2-PACKED state updates (FFMA2/FADD2/FMUL2 on sm_103a).
// B=128, T=1024, C=128 (blank=127), L=128, S=257.
//
// One CTA (128 threads = 4 warps) per batch element:
//   warp 0: FORWARD DP rows 0..511   (states packed even/odd f32x2 pairs)
//   warp 1: BACKWARD DP rows 1023..512 (same packing)
//   warp 2/3: softmax log-normalizer halves.
// Combine at t0=511: loglik = log(sum_s alpha[s]*beta^[s]) - zsum.
// Numerics identical to the round-13 kernel (same ops elementwise).

#define T_   1024
#define C_   128
#define L_   128
#define EPS_ 1e-7f
#define CEPS_ (128.0f * 1e-7f)
#define FULL 0xffffffffu
#define LN2  0.6931471805599453f

typedef unsigned long long u64c;

#define PK(o, l, h)    asm("mov.b64 %0,{%1,%2};" : "=l"(o) : "f"(l), "f"(h))
#define UNPK(l, h, i)  asm("mov.b64 {%0,%1},%2;" : "=f"(l), "=f"(h) : "l"(i))
#define ADD2(o, a, b)  asm("add.rn.f32x2 %0,%1,%2;" : "=l"(o) : "l"(a), "l"(b))
#define MUL2(o, a, b)  asm("mul.rn.f32x2 %0,%1,%2;" : "=l"(o) : "l"(a), "l"(b))
#define FMA2(o, a, b, c) \
    asm("fma.rn.f32x2 %0,%1,%2,%3;" : "=l"(o) : "l"(a), "l"(b), "l"(c))

// ---------------- FORWARD packed step ----------------
// States: E01=(a0,a2) E23=(a4,a6) O01=(a1,a3) O23=(a5,a7), a256 scalar.
#define FSTEP(PH, t, RS, RF, PREP) {                                           \
    float a1f, a3f, a5f, a7f;                                                  \
    UNPK(a1f, a3f, O01); UNPK(a5f, a7f, O23);                                  \
    u64c S01, S23;                                                             \
    PK(S01, pm1, a1f); PK(S23, a3f, a5f);                                      \
    u64c sO23, tO23, nO23;                                                     \
    ADD2(sO23, O23, E23);            /* (a5+a4, a7+a6) */                      \
    FMA2(tO23, SK23, S23, sO23);     /* (+sk2*a3, +sk3*a5) */                  \
    MUL2(nO23, tO23, Q23);           /* (n5, n7) */                            \
    float n5f, n7f; UNPK(n5f, n7f, nO23); (void)n5f;                           \
    const float a7s = __shfl_up_sync(FULL, n7f, 1);                            \
    u64c sO01, tO01, nO01;                                                     \
    ADD2(sO01, O01, E01);            /* (a1+a0, a3+a2) */                      \
    FMA2(tO01, SK01, S01, sO01);     /* (+sk0*pm1, +sk1*a1) */                 \
    MUL2(nO01, tO01, Q01);           /* (n1, n3) */                            \
    u64c sE01, sE23, nE01, nE23;                                               \
    ADD2(sE01, E01, S01);            /* (a0+pm1, a2+a1) */                     \
    ADD2(sE23, E23, S23);            /* (a4+a3, a6+a5) */                      \
    MUL2(nE01, sE01, PB2);           /* (n0, n2) */                            \
    MUL2(nE23, sE23, PB2);           /* (n4, n6) */                            \
    const float n8 = (a256 + a7f) * pbs;                                       \
    if (RF) {                                                                  \
        const float* r8 = row + (size_t)((t) + 8) * C_;                        \
        gbr[PH][0] = r8[cls0]; gbr[PH][1] = r8[cls1];                          \
        gbr[PH][2] = r8[cls2]; gbr[PH][3] = r8[cls3];                          \
        pbr[PH]    = r8[C_ - 1];                                               \
    }                                                                          \
    E01 = nE01; E23 = nE23; O01 = nO01; O23 = nO23; a256 = n8;                 \
    float sckq = 1.f;                                                          \
    if (RS) {                                                                  \
        float x0, x2, x4, x6, x1, x3;                                          \
        UNPK(x0, x2, nE01); UNPK(x4, x6, nE23); UNPK(x1, x3, nO01);            \
        float m = fmaxf(fmaxf(fmaxf(x0, x1), fmaxf(x2, x3)),                   \
                        fmaxf(fmaxf(x4, n5f), fmaxf(x6, n7f)));                \
        m = fmaxf(m, n8);                                                      \
        const bool has = (m > 0.f);                                            \
        const int k = has ? ((__float_as_int(m) >> 23) - 127) : 0;             \
        sckq = __int_as_float((127 - k) << 23);                                \
        e = has ? (e + k) : e_up_save;                                         \
        e_up_save = __shfl_up_sync(FULL, e, 1);                                \
        const int bexp = min(max(e_up_save - e + 127, 0), 254);                \
        sc_pm_nx = (lane == 0) ? 0.f : __int_as_float(bexp << 23);             \
    }                                                                          \
    pm1 = a7s * sc_pm;                                                         \
    if (RS) sc_pm = sc_pm_nx;                                                  \
    if (PREP) {                                                                \
        const int NP = ((t) + 1) & 7;                                          \
        u64c r01, r23;                                                         \
        PK(r01, gbr[NP][0], gbr[NP][1]); PK(r23, gbr[NP][2], gbr[NP][3]);      \
        ADD2(Q01, r01, EPS2); ADD2(Q23, r23, EPS2);                            \
        pbs = pbr[NP] + EPS_;                                                  \
        if (RS) {                                                              \
            u64c SKQ2; PK(SKQ2, sckq, sckq);                                   \
            MUL2(Q01, Q01, SKQ2); MUL2(Q23, Q23, SKQ2);                        \
            pbs *= sckq;                                                       \
        }                                                                      \
        PK(PB2, pbs, pbs);                                                     \
    } }

#define FBLK8(tb) \
    FSTEP(0,(tb)+0,0,1,1) FSTEP(1,(tb)+1,0,1,1) FSTEP(2,(tb)+2,0,1,1) \
    FSTEP(3,(tb)+3,1,1,1) FSTEP(4,(tb)+4,0,1,1) FSTEP(5,(tb)+5,0,1,1) \
    FSTEP(6,(tb)+6,0,1,1) FSTEP(7,(tb)+7,1,1,1)
#define FBLK8_LAST(tb) \
    FSTEP(0,(tb)+0,0,0,1) FSTEP(1,(tb)+1,0,0,1) FSTEP(2,(tb)+2,0,0,1) \
    FSTEP(3,(tb)+3,1,0,1) FSTEP(4,(tb)+4,0,0,1) FSTEP(5,(tb)+5,0,0,1) \
    FSTEP(6,(tb)+6,0,0,1) FSTEP(7,(tb)+7,0,0,0)

// ---------------- BACKWARD packed step ----------------
// States: bE01=(b0,b2) bE23=(b4,b6) bO01=(b1,b3) bO23=(b5,b7), b256 scalar.
#define BSTEP(SL, u, RS, RF, PREP) {                                           \
    float b0f, b2f, b4f, b6f, b1f, b3f, b5f, b7f;                              \
    UNPK(b0f, b2f, bE01); UNPK(b4f, b6f, bE23);                                \
    UNPK(b1f, b3f, bO01); UNPK(b5f, b7f, bO23); (void)b0f; (void)b1f;          \
    u64c SH24, SH35;                                                           \
    PK(SH24, b2f, b4f); PK(SH35, b3f, b5f);                                    \
    u64c tE01, tE23, nE01b, nE23b;                                             \
    MUL2(tE01, bE01, DPB2); FMA2(nE01b, DQ01, bO01, tE01);  /* (b0n,b2n) */    \
    MUL2(tE23, bE23, DPB2); FMA2(nE23b, DQ23, bO23, tE23);  /* (b4n,b6n) */    \
    u64c u1, u2, nO01b;                                                        \
    MUL2(u1, DQ01, bO01);            /* (dq0*b1, dq1*b3) */                    \
    FMA2(u2, DPB2, SH24, u1);        /* + (dpb*b2, dpb*b4) */                  \
    FMA2(nO01b, DQS12, SH35, u2);    /* (b1n, b3n) */                          \
    u64c xw; MUL2(xw, DQ23, bO23);   /* (dq2*b5, dq3*b7) */                    \
    float xlo, xhi; UNPK(xlo, xhi, xw);                                        \
    const float b5n = fmaf(dqs3, b7f, fmaf(dpbs, b6f, xlo));                   \
    const float b7n = xhi + comb;                                              \
    u64c nO23b; PK(nO23b, b5n, b7n);                                           \
    if (RF) {                                                                  \
        const float* r8 = row + (size_t)(1015 - (u)) * C_;                     \
        dbr[SL][0] = r8[cls0]; dbr[SL][1] = r8[cls1];                          \
        dbr[SL][2] = r8[cls2]; dbr[SL][3] = r8[cls3];                          \
        dpr[SL]    = r8[C_ - 1];                                               \
    }                                                                          \
    bE01 = nE01b; bE23 = nE23b; bO01 = nO01b; bO23 = nO23b; b256 = c256;       \
    float sckq = 1.f;                                                          \
    if (RS) {                                                                  \
        float y0, y2, y4, y6, y1, y3;                                          \
        UNPK(y0, y2, nE01b); UNPK(y4, y6, nE23b); UNPK(y1, y3, nO01b);         \
        float m = fmaxf(fmaxf(fmaxf(y0, y1), fmaxf(y2, y3)),                   \
                        fmaxf(fmaxf(y4, b5n), fmaxf(y6, b7n)));                \
        m = fmaxf(m, b256);                                                    \
        const bool has = (m > 0.f);                                            \
        const int k = has ? ((__float_as_int(m) >> 23) - 127) : 0;             \
        sckq = __int_as_float((127 - k) << 23);                                \
        eb = has ? (eb + k) : e_dn_save;                                       \
        e_dn_save = __shfl_down_sync(FULL, eb, 1);                             \
        const int bexp = min(max(e_dn_save - eb + 127, 0), 254);               \
        sc_cm = __int_as_float(bexp << 23);                                    \
    }                                                                          \
    if (PREP) {                                                                \
        const int NP = ((u) + 1) & 7;                                          \
        u64c r01, r23;                                                         \
        PK(r01, dbr[NP][0], dbr[NP][1]); PK(r23, dbr[NP][2], dbr[NP][3]);      \
        ADD2(DQ01, r01, EPS2); ADD2(DQ23, r23, EPS2);                          \
        dpbs = dpr[NP] + EPS_;                                                 \
        if (RS) {                                                              \
            u64c SKQ2; PK(SKQ2, sckq, sckq);                                   \
            MUL2(DQ01, DQ01, SKQ2); MUL2(DQ23, DQ23, SKQ2);                    \
            dpbs *= sckq;                                                      \
        }                                                                      \
        PK(DPB2, dpbs, dpbs);                                                  \
        float dq0f, dq1f, dq2f, dq3f;                                          \
        UNPK(dq0f, dq1f, DQ01); UNPK(dq2f, dq3f, DQ23);                        \
        u64c d12; PK(d12, dq1f, dq2f);                                         \
        MUL2(DQS12, SKB12, d12);     /* (sk1*dq1, sk2*dq2) */                  \
        dqs3 = sk3 * dq3f;                                                     \
        float b0nn, b2nn, b1nn, b3nn;                                          \
        UNPK(b0nn, b2nn, bE01); UNPK(b1nn, b3nn, bO01);                        \
        (void)b2nn; (void)b3nn;                                                \
        const float gcomb = fmaf(sk0 * dq0f, b1nn, dpbs * b0nn);               \
        c256 = dpbs * b256;                                                    \
        const float gsh = __shfl_down_sync(FULL, gcomb, 1);                    \
        comb = (lane == 31) ? c256 : gsh * sc_cm;                              \
    } }

#define BBLK8(ub) \
    BSTEP(0,(ub)+0,0,1,1) BSTEP(1,(ub)+1,0,1,1) BSTEP(2,(ub)+2,0,1,1) \
    BSTEP(3,(ub)+3,1,1,1) BSTEP(4,(ub)+4,0,1,1) BSTEP(5,(ub)+5,0,1,1) \
    BSTEP(6,(ub)+6,0,1,1) BSTEP(7,(ub)+7,1,1,1)
#define BBLK8_LAST(ub) \
    BSTEP(0,(ub)+0,0,0,1) BSTEP(1,(ub)+1,0,0,1) BSTEP(2,(ub)+2,0,0,1) \
    BSTEP(3,(ub)+3,1,0,1) BSTEP(4,(ub)+4,0,0,1) BSTEP(5,(ub)+5,0,0,1) \
    BSTEP(6,(ub)+6,0,0,1) BSTEP(7,(ub)+7,0,0,0)

// softmax log-normalizer over 512 rows starting at zrow (lane-offset applied)
__device__ __forceinline__ float zhalf(const float* __restrict__ zrow)
{
    float4 ring[4][4];
#pragma unroll
    for (int j = 0; j < 4; j++) {
        const float* p = zrow + (size_t)j * 4 * C_;
        ring[j][0] = *(const float4*)(p + 0);
        ring[j][1] = *(const float4*)(p + 4);
        ring[j][2] = *(const float4*)(p + 8);
        ring[j][3] = *(const float4*)(p + 12);
    }
    float zs = 0.f;
    for (int r8 = 0; r8 < 128; r8 += 8) {
        float zp = 1.f;
#pragma unroll
        for (int rr = 0; rr < 8; rr++) {
            const int slot = rr & 3;
            float4 v0 = ring[slot][0], v1 = ring[slot][1],
                   v2 = ring[slot][2], v3 = ring[slot][3];
            const int r = r8 + rr;
            if (r + 4 < 128) {
                const float* p = zrow + (size_t)(r + 4) * 4 * C_;
                ring[slot][0] = *(const float4*)(p + 0);
                ring[slot][1] = *(const float4*)(p + 4);
                ring[slot][2] = *(const float4*)(p + 8);
                ring[slot][3] = *(const float4*)(p + 12);
            }
            float s = ((v0.x + v0.y) + (v0.z + v0.w))
                    + ((v1.x + v1.y) + (v1.z + v1.w))
                    + ((v2.x + v2.y) + (v2.z + v2.w))
                    + ((v3.x + v3.y) + (v3.z + v3.w));
            s += __shfl_xor_sync(FULL, s, 1);
            s += __shfl_xor_sync(FULL, s, 2);
            s += __shfl_xor_sync(FULL, s, 4);
            zp *= (s + CEPS_);
        }
        zs += __logf(zp);
    }
    zs += __shfl_xor_sync(FULL, zs, 8);
    zs += __shfl_xor_sync(FULL, zs, 16);
    return zs;
}

__global__ __launch_bounds__(128, 1)
void ctc_fb2_kernel(const int* __restrict__ y_true,
                    const float* __restrict__ y_pred,
                    float* __restrict__ out)
{
    __shared__ float sb_b[32 * 9];
    __shared__ int   sb_e[32];
    __shared__ float s_z[2];

    const int b    = blockIdx.x;
    const int tid  = threadIdx.x;
    const int lane = tid & 31;
    const int wrp  = tid >> 5;
    const float* __restrict__ row = y_pred + (size_t)b * T_ * C_;

    // per-lane label config (shared by both DP warps)
    int4 c4 = *(const int4*)(y_true + b * L_ + 4 * lane);
    const int cls0 = c4.x, cls1 = c4.y, cls2 = c4.z, cls3 = c4.w;
    int clsm1 = __shfl_up_sync(FULL, cls3, 1);
    const float sk0 = (lane > 0 && cls0 != clsm1) ? 1.f : 0.f;
    const float sk1 = (cls1 != cls0) ? 1.f : 0.f;
    const float sk2 = (cls2 != cls1) ? 1.f : 0.f;
    const float sk3 = (cls3 != cls2) ? 1.f : 0.f;

    const float epsf = EPS_;
    u64c EPS2; PK(EPS2, epsf, epsf);

    // forward packed state (function scope: survives to the combine)
    u64c E01, E23, O01, O23;
    {
        const float zf = 0.f;
        PK(E01, zf, zf); PK(E23, zf, zf); PK(O01, zf, zf); PK(O23, zf, zf);
    }
    float a256 = 0.f;
    int   e = 0;

    if (wrp == 0) {
        // ---------------- FORWARD: rows 0..511 ----------------
        u64c SK01, SK23; PK(SK01, sk0, sk1); PK(SK23, sk2, sk3);
        float gbr[8][4];
        float pbr[8];
#pragma unroll
        for (int j = 0; j < 8; j++) {
            const float* r = row + (size_t)j * C_;
            gbr[j][0] = r[cls0]; gbr[j][1] = r[cls1];
            gbr[j][2] = r[cls2]; gbr[j][3] = r[cls3];
            pbr[j]    = r[C_ - 1];
        }
        int   e_up_save = 0;
        float sc_pm = (lane == 0) ? 0.f : 1.f;
        float sc_pm_nx = sc_pm;
        float pm1 = 0.f;
        u64c Q01, Q23, PB2;
        float pbs;

        // t = 0 init: states 0 (blank) and 1 (first label) on lane 0
        {
            const float q00 = gbr[0][0] + EPS_;
            const float pb0 = pbr[0] + EPS_;
            const float a0i = (lane == 0) ? pb0 : 0.f;
            const float a1i = (lane == 0) ? q00 : 0.f;
            const float zf = 0.f;
            PK(E01, a0i, zf); PK(O01, a1i, zf);
            const float* r8 = row + (size_t)8 * C_;
            gbr[0][0] = r8[cls0]; gbr[0][1] = r8[cls1];
            gbr[0][2] = r8[cls2]; gbr[0][3] = r8[cls3];
            pbr[0]    = r8[C_ - 1];
            // prep operands for t = 1
            u64c r01, r23;
            PK(r01, gbr[1][0], gbr[1][1]); PK(r23, gbr[1][2], gbr[1][3]);
            ADD2(Q01, r01, EPS2); ADD2(Q23, r23, EPS2);
            pbs = pbr[1] + EPS_;
            PK(PB2, pbs, pbs);
        }

        // t = 1..7 (renorm at 3,7)
        FSTEP(1,1,0,1,1) FSTEP(2,2,0,1,1) FSTEP(3,3,1,1,1) FSTEP(4,4,0,1,1)
        FSTEP(5,5,0,1,1) FSTEP(6,6,0,1,1) FSTEP(7,7,1,1,1)
        // t = 8..503
        for (int tb = 8; tb < 504; tb += 8) { FBLK8(tb) }
        // t = 504..511
        FBLK8_LAST(504)
    } else if (wrp == 1) {
        // ---------------- BACKWARD: rows 1023..512 ----------------
        u64c SKB12; PK(SKB12, sk1, sk2);
        float dbr[8][4];
        float dpr[8];
#pragma unroll
        for (int j = 0; j < 8; j++) {
            const float* r = row + (size_t)(1023 - j) * C_;
            dbr[j][0] = r[cls0]; dbr[j][1] = r[cls1];
            dbr[j][2] = r[cls2]; dbr[j][3] = r[cls3];
            dpr[j]    = r[C_ - 1];
        }
        u64c bE01, bE23, bO01, bO23;
        {
            const float zf = 0.f;
            const float b7i = (lane == 31) ? 1.f : 0.f;
            PK(bE01, zf, zf); PK(bE23, zf, zf);
            PK(bO01, zf, zf); PK(bO23, zf, b7i);
        }
        float b256 = (lane == 31) ? 1.f : 0.f;
        int   eb = 0, e_dn_save = 0;
        float sc_cm = 1.f;
        u64c DQ01, DQ23, DPB2, DQS12;
        float dpbs, dqs3, c256, comb;

        // init prep for update u=0 (row 1023, slot 0)
        {
            u64c r01, r23;
            PK(r01, dbr[0][0], dbr[0][1]); PK(r23, dbr[0][2], dbr[0][3]);
            ADD2(DQ01, r01, EPS2); ADD2(DQ23, r23, EPS2);
            dpbs = dpr[0] + EPS_;
            PK(DPB2, dpbs, dpbs);
            float dq0f, dq1f, dq2f, dq3f;
            UNPK(dq0f, dq1f, DQ01); UNPK(dq2f, dq3f, DQ23);
            u64c d12; PK(d12, dq1f, dq2f);
            MUL2(DQS12, SKB12, d12);
            dqs3 = sk3 * dq3f;
            float b0i, b2i, b1i, b3i;
            UNPK(b0i, b2i, bE01); UNPK(b1i, b3i, bO01);
            (void)b2i; (void)b3i;
            const float gcomb = fmaf(sk0 * dq0f, b1i, dpbs * b0i);  // = 0
            c256 = dpbs * b256;
            const float gsh = __shfl_down_sync(FULL, gcomb, 1);
            comb = (lane == 31) ? c256 : gsh * sc_cm;
        }

        // u = 0..503
        for (int ub = 0; ub < 504; ub += 8) { BBLK8(ub) }
        // u = 504..511
        BBLK8_LAST(504)

        // publish beta^_511 (per-lane scale 2^eb)
        {
            float p0, p2, p4, p6, p1, p3, p5, p7;
            UNPK(p0, p2, bE01); UNPK(p4, p6, bE23);
            UNPK(p1, p3, bO01); UNPK(p5, p7, bO23);
            sb_b[lane * 9 + 0] = p0; sb_b[lane * 9 + 1] = p1;
            sb_b[lane * 9 + 2] = p2; sb_b[lane * 9 + 3] = p3;
            sb_b[lane * 9 + 4] = p4; sb_b[lane * 9 + 5] = p5;
            sb_b[lane * 9 + 6] = p6; sb_b[lane * 9 + 7] = p7;
            sb_b[lane * 9 + 8] = b256;
            sb_e[lane] = eb;
        }
    } else if (wrp == 2) {
        float zs = zhalf(row + (size_t)(lane >> 3) * C_ + (size_t)(lane & 7) * 16);
        if (lane == 0) s_z[0] = zs;
    } else {
        float zs = zhalf(row + (size_t)512 * C_
                         + (size_t)(lane >> 3) * C_ + (size_t)(lane & 7) * 16);
        if (lane == 0) s_z[1] = zs;
    }

    __syncthreads();

    // ---------------- combine on warp 0 ----------------
    if (wrp == 0) {
        float a0, a2, a4, a6, a1, a3, a5, a7;
        UNPK(a0, a2, E01); UNPK(a4, a6, E23);
        UNPK(a1, a3, O01); UNPK(a5, a7, O23);
        const float* bb = sb_b + lane * 9;
        float dot = a0 * bb[0] + a1 * bb[1] + a2 * bb[2] + a3 * bb[3]
                  + a4 * bb[4] + a5 * bb[5] + a6 * bb[6] + a7 * bb[7];
        if (lane == 31) dot = fmaf(a256, bb[8], dot);
        const int el = e + sb_e[lane];
        int elm = (dot > 0.f) ? el : -1000000;
        elm = max(elm, __shfl_xor_sync(FULL, elm, 1));
        elm = max(elm, __shfl_xor_sync(FULL, elm, 2));
        elm = max(elm, __shfl_xor_sync(FULL, elm, 4));
        elm = max(elm, __shfl_xor_sync(FULL, elm, 8));
        elm = max(elm, __shfl_xor_sync(FULL, elm, 16));
        const int d = el - elm + 127;
        const float sc = (dot > 0.f && d >= 1) ? __int_as_float(d << 23) : 0.f;
        float s = dot * sc;
        s += __shfl_xor_sync(FULL, s, 1);
        s += __shfl_xor_sync(FULL, s, 2);
        s += __shfl_xor_sync(FULL, s, 4);
        s += __shfl_xor_sync(FULL, s, 8);
        s += __shfl_xor_sync(FULL, s, 16);
        if (lane == 0) {
            float ll = __logf(s) + (float)elm * LN2 - (s_z[0] + s_z[1]);
            out[b] = -ll;
        }
    }
}

extern "C" void kernel_launch(void* const* d_in, const int* in_sizes, int n_in,
                              void* d_out, int out_size)
{
    const int* y_true;
    const float* y_pred;
    if (in_sizes[0] == 128 * L_) {            // y_true: [B,L] int32
        y_true = (const int*)d_in[0];
        y_pred = (const float*)d_in[1];
    } else {
        y_true = (const int*)d_in[1];
        y_pred = (const float*)d_in[0];
    }
    const int B = out_size;                    // [B,1] float32
    ctc_fb2_kernel<<<B, 128>>>(y_true, y_pred, (float*)d_out);
}

// round 15
// speedup vs baseline: 1.0849x; 1.0849x over previous
#include <cuda_runtime.h>

// CTC forward loss — forward/backward split with BALANCED cut at t0=559:
// forward (cheaper/step) runs 559 steps, backward (costlier/step) runs 464.
// B=128, T=1024, C=128 (blank=127), L=128, S=257.
//
// One CTA (128 threads = 4 warps) per batch element:
//   warp 0: FORWARD DP rows 0..559   -> alpha_559 (per-lane BFP scale e)
//   warp 1: BACKWARD DP rows 1023..560 -> beta^_559 (per-lane scale eb)
//   warp 2/3: softmax log-normalizer halves (rows 0..511 / 512..1023).
// Combine: loglik = log(sum_s alpha_559[s]*beta^_559[s]) - zsum.
//
// DP machinery identical to the round-13 kernel (raw-LDG 8-deep ring,
// software-pipelined operand prep, renorm every 4 steps, single-shfl
// exponent bookkeeping, pipelined cross-lane handoff).

#define T_   1024
#define C_   128
#define L_   128
#define EPS_ 1e-7f
#define CEPS_ (128.0f * 1e-7f)
#define FULL 0xffffffffu
#define LN2  0.6931471805599453f

// ---------------- FORWARD step ----------------
#define FSTEP(PH, t, RS, RF, PREP) {                                           \
    const float n7 = fmaf(sk3, a5, a7 + a6) * cq3;                             \
    const float a7s = __shfl_up_sync(FULL, n7, 1);                             \
    const float n8 = (a256 + a7) * cpb;                                        \
    const float n0 = (a0 + pm1) * cpb;                                         \
    const float n1 = fmaf(sk0, pm1, a1 + a0) * cq0;                            \
    const float n2 = (a2 + a1) * cpb;                                          \
    const float n3 = fmaf(sk1, a1, a3 + a2) * cq1;                             \
    const float n4 = (a4 + a3) * cpb;                                          \
    const float n5 = fmaf(sk2, a3, a5 + a4) * cq2;                             \
    const float n6 = (a6 + a5) * cpb;                                          \
    if (RF) {                                                                  \
        const float* r8 = row + (size_t)((t) + 8) * C_;                        \
        gbr[PH][0] = r8[cls0]; gbr[PH][1] = r8[cls1];                          \
        gbr[PH][2] = r8[cls2]; gbr[PH][3] = r8[cls3];                          \
        pbr[PH]    = r8[C_ - 1];                                               \
    }                                                                          \
    a0 = n0; a1 = n1; a2 = n2; a3 = n3;                                        \
    a4 = n4; a5 = n5; a6 = n6; a7 = n7; a256 = n8;                             \
    float sckq = 1.f;                                                          \
    if (RS) {                                                                  \
        float m = fmaxf(fmaxf(fmaxf(n0, n1), fmaxf(n2, n3)),                   \
                        fmaxf(fmaxf(n4, n5), fmaxf(n6, n7)));                  \
        m = fmaxf(m, n8);                                                      \
        const bool has = (m > 0.f);                                            \
        const int k = has ? ((__float_as_int(m) >> 23) - 127) : 0;             \
        sckq = __int_as_float((127 - k) << 23);                                \
        e = has ? (e + k) : e_up_save;                                         \
        e_up_save = __shfl_up_sync(FULL, e, 1);                                \
        const int bexp = min(max(e_up_save - e + 127, 0), 254);                \
        sc_pm_nx = (lane == 0) ? 0.f : __int_as_float(bexp << 23);             \
    }                                                                          \
    pm1 = a7s * sc_pm;                                                         \
    if (RS) sc_pm = sc_pm_nx;                                                  \
    if (PREP) {                                                                \
        const int NP = ((t) + 1) & 7;                                          \
        cq0 = gbr[NP][0] + EPS_; cq1 = gbr[NP][1] + EPS_;                      \
        cq2 = gbr[NP][2] + EPS_; cq3 = gbr[NP][3] + EPS_;                      \
        cpb = pbr[NP] + EPS_;                                                  \
        if (RS) { cq0 *= sckq; cq1 *= sckq; cq2 *= sckq;                       \
                  cq3 *= sckq; cpb *= sckq; }                                  \
    } }

#define FBLK8(tb) \
    FSTEP(0,(tb)+0,0,1,1) FSTEP(1,(tb)+1,0,1,1) FSTEP(2,(tb)+2,0,1,1) \
    FSTEP(3,(tb)+3,1,1,1) FSTEP(4,(tb)+4,0,1,1) FSTEP(5,(tb)+5,0,1,1) \
    FSTEP(6,(tb)+6,0,1,1) FSTEP(7,(tb)+7,1,1,1)
#define FBLK8_LAST(tb) \
    FSTEP(0,(tb)+0,0,0,1) FSTEP(1,(tb)+1,0,0,1) FSTEP(2,(tb)+2,0,0,1) \
    FSTEP(3,(tb)+3,1,0,1) FSTEP(4,(tb)+4,0,0,1) FSTEP(5,(tb)+5,0,0,1) \
    FSTEP(6,(tb)+6,0,0,1) FSTEP(7,(tb)+7,0,0,0)

// ---------------- BACKWARD step ----------------
// Update u computes beta^ at time 1022-u, consuming row 1023-u.
#define BSTEP(SL, u, RS, RF, PREP) {                                           \
    const float b0n = fmaf(dq0, b1, dpb * b0);                                 \
    const float b1n = fmaf(dqs1, b3, fmaf(dpb, b2, dq0 * b1));                 \
    const float b2n = fmaf(dq1, b3, dpb * b2);                                 \
    const float b3n = fmaf(dqs2, b5, fmaf(dpb, b4, dq1 * b3));                 \
    const float b4n = fmaf(dq2, b5, dpb * b4);                                 \
    const float b5n = fmaf(dqs3, b7, fmaf(dpb, b6, dq2 * b5));                 \
    const float b6n = fmaf(dq3, b7, dpb * b6);                                 \
    const float b7n = fmaf(dq3, b7, comb);                                     \
    if (RF) {                                                                  \
        const float* r8 = row + (size_t)(1015 - (u)) * C_;                     \
        dbr[SL][0] = r8[cls0]; dbr[SL][1] = r8[cls1];                          \
        dbr[SL][2] = r8[cls2]; dbr[SL][3] = r8[cls3];                          \
        dpr[SL]    = r8[C_ - 1];                                               \
    }                                                                          \
    b0 = b0n; b1 = b1n; b2 = b2n; b3 = b3n;                                    \
    b4 = b4n; b5 = b5n; b6 = b6n; b7 = b7n; b256 = c256;                       \
    float sckq = 1.f;                                                          \
    if (RS) {                                                                  \
        float m = fmaxf(fmaxf(fmaxf(b0n, b1n), fmaxf(b2n, b3n)),               \
                        fmaxf(fmaxf(b4n, b5n), fmaxf(b6n, b7n)));              \
        m = fmaxf(m, b256);                                                    \
        const bool has = (m > 0.f);                                            \
        const int k = has ? ((__float_as_int(m) >> 23) - 127) : 0;             \
        sckq = __int_as_float((127 - k) << 23);                                \
        eb = has ? (eb + k) : e_dn_save;                                       \
        e_dn_save = __shfl_down_sync(FULL, eb, 1);                             \
        const int bexp = min(max(e_dn_save - eb + 127, 0), 254);               \
        sc_cm = __int_as_float(bexp << 23);                                    \
    }                                                                          \
    if (PREP) {                                                                \
        const int NP = ((u) + 1) & 7;                                          \
        dq0 = dbr[NP][0] + EPS_; dq1 = dbr[NP][1] + EPS_;                      \
        dq2 = dbr[NP][2] + EPS_; dq3 = dbr[NP][3] + EPS_;                      \
        dpb = dpr[NP] + EPS_;                                                  \
        if (RS) { dq0 *= sckq; dq1 *= sckq; dq2 *= sckq;                       \
                  dq3 *= sckq; dpb *= sckq; }                                  \
        dqs1 = sk1 * dq1; dqs2 = sk2 * dq2; dqs3 = sk3 * dq3;                  \
        const float gcomb = fmaf(sk0 * dq0, b1, dpb * b0);                     \
        c256 = dpb * b256;                                                     \
        const float gsh = __shfl_down_sync(FULL, gcomb, 1);                    \
        comb = (lane == 31) ? c256 : gsh * sc_cm;                              \
    } }

#define BBLK8(ub) \
    BSTEP(0,(ub)+0,0,1,1) BSTEP(1,(ub)+1,0,1,1) BSTEP(2,(ub)+2,0,1,1) \
    BSTEP(3,(ub)+3,1,1,1) BSTEP(4,(ub)+4,0,1,1) BSTEP(5,(ub)+5,0,1,1) \
    BSTEP(6,(ub)+6,0,1,1) BSTEP(7,(ub)+7,1,1,1)
#define BBLK8_LAST(ub) \
    BSTEP(0,(ub)+0,0,0,1) BSTEP(1,(ub)+1,0,0,1) BSTEP(2,(ub)+2,0,0,1) \
    BSTEP(3,(ub)+3,1,0,1) BSTEP(4,(ub)+4,0,0,1) BSTEP(5,(ub)+5,0,0,1) \
    BSTEP(6,(ub)+6,0,0,1) BSTEP(7,(ub)+7,0,0,0)

// softmax log-normalizer over 512 rows starting at zrow (lane-offset applied)
__device__ __forceinline__ float zhalf(const float* __restrict__ zrow)
{
    float4 ring[4][4];
#pragma unroll
    for (int j = 0; j < 4; j++) {
        const float* p = zrow + (size_t)j * 4 * C_;
        ring[j][0] = *(const float4*)(p + 0);
        ring[j][1] = *(const float4*)(p + 4);
        ring[j][2] = *(const float4*)(p + 8);
        ring[j][3] = *(const float4*)(p + 12);
    }
    float zs = 0.f;
    for (int r8 = 0; r8 < 128; r8 += 8) {
        float zp = 1.f;
#pragma unroll
        for (int rr = 0; rr < 8; rr++) {
            const int slot = rr & 3;
            float4 v0 = ring[slot][0], v1 = ring[slot][1],
                   v2 = ring[slot][2], v3 = ring[slot][3];
            const int r = r8 + rr;
            if (r + 4 < 128) {
                const float* p = zrow + (size_t)(r + 4) * 4 * C_;
                ring[slot][0] = *(const float4*)(p + 0);
                ring[slot][1] = *(const float4*)(p + 4);
                ring[slot][2] = *(const float4*)(p + 8);
                ring[slot][3] = *(const float4*)(p + 12);
            }
            float s = ((v0.x + v0.y) + (v0.z + v0.w))
                    + ((v1.x + v1.y) + (v1.z + v1.w))
                    + ((v2.x + v2.y) + (v2.z + v2.w))
                    + ((v3.x + v3.y) + (v3.z + v3.w));
            s += __shfl_xor_sync(FULL, s, 1);
            s += __shfl_xor_sync(FULL, s, 2);
            s += __shfl_xor_sync(FULL, s, 4);
            zp *= (s + CEPS_);
        }
        zs += __logf(zp);
    }
    zs += __shfl_xor_sync(FULL, zs, 8);
    zs += __shfl_xor_sync(FULL, zs, 16);
    return zs;
}

__global__ __launch_bounds__(128, 1)
void ctc_fb3_kernel(const int* __restrict__ y_true,
                    const float* __restrict__ y_pred,
                    float* __restrict__ out)
{
    __shared__ float sb_b[32 * 9];
    __shared__ int   sb_e[32];
    __shared__ float s_z[2];

    const int b    = blockIdx.x;
    const int tid  = threadIdx.x;
    const int lane = tid & 31;
    const int wrp  = tid >> 5;
    const float* __restrict__ row = y_pred + (size_t)b * T_ * C_;

    // per-lane label config (shared by both DP warps)
    int4 c4 = *(const int4*)(y_true + b * L_ + 4 * lane);
    const int cls0 = c4.x, cls1 = c4.y, cls2 = c4.z, cls3 = c4.w;
    int clsm1 = __shfl_up_sync(FULL, cls3, 1);
    const float sk0 = (lane > 0 && cls0 != clsm1) ? 1.f : 0.f;
    const float sk1 = (cls1 != cls0) ? 1.f : 0.f;
    const float sk2 = (cls2 != cls1) ? 1.f : 0.f;
    const float sk3 = (cls3 != cls2) ? 1.f : 0.f;

    // forward DP state (function scope: survives to the combine)
    float a0 = 0.f, a1 = 0.f, a2 = 0.f, a3 = 0.f,
          a4 = 0.f, a5 = 0.f, a6 = 0.f, a7 = 0.f, a256 = 0.f;
    int   e = 0;

    if (wrp == 0) {
        // ---------------- FORWARD: rows 0..559 ----------------
        float gbr[8][4];
        float pbr[8];
#pragma unroll
        for (int j = 0; j < 8; j++) {
            const float* r = row + (size_t)j * C_;
            gbr[j][0] = r[cls0]; gbr[j][1] = r[cls1];
            gbr[j][2] = r[cls2]; gbr[j][3] = r[cls3];
            pbr[j]    = r[C_ - 1];
        }
        int   e_up_save = 0;
        float sc_pm = (lane == 0) ? 0.f : 1.f;
        float sc_pm_nx = sc_pm;
        float pm1 = 0.f;
        float cq0, cq1, cq2, cq3, cpb;

        // t = 0 init
        cq0 = gbr[0][0] + EPS_;
        cpb = pbr[0] + EPS_;
        if (lane == 0) { a0 = cpb; a1 = cq0; }
        {
            const float* r8 = row + (size_t)8 * C_;
            gbr[0][0] = r8[cls0]; gbr[0][1] = r8[cls1];
            gbr[0][2] = r8[cls2]; gbr[0][3] = r8[cls3];
            pbr[0]    = r8[C_ - 1];
        }
        cq0 = gbr[1][0] + EPS_; cq1 = gbr[1][1] + EPS_;
        cq2 = gbr[1][2] + EPS_; cq3 = gbr[1][3] + EPS_;
        cpb = pbr[1] + EPS_;

        // t = 1..7
        FSTEP(1,1,0,1,1) FSTEP(2,2,0,1,1) FSTEP(3,3,1,1,1) FSTEP(4,4,0,1,1)
        FSTEP(5,5,0,1,1) FSTEP(6,6,0,1,1) FSTEP(7,7,1,1,1)
        // t = 8..551
        for (int tb = 8; tb < 552; tb += 8) { FBLK8(tb) }
        // t = 552..559 (no refills; ring already holds rows 552..559)
        FBLK8_LAST(552)
    } else if (wrp == 1) {
        // ---------------- BACKWARD: rows 1023..560 ----------------
        float dbr[8][4];
        float dpr[8];
#pragma unroll
        for (int j = 0; j < 8; j++) {
            const float* r = row + (size_t)(1023 - j) * C_;
            dbr[j][0] = r[cls0]; dbr[j][1] = r[cls1];
            dbr[j][2] = r[cls2]; dbr[j][3] = r[cls3];
            dpr[j]    = r[C_ - 1];
        }
        float b0 = 0.f, b1 = 0.f, b2 = 0.f, b3 = 0.f,
              b4 = 0.f, b5 = 0.f, b6 = 0.f;
        float b7   = (lane == 31) ? 1.f : 0.f;   // beta^_1023[255]
        float b256 = (lane == 31) ? 1.f : 0.f;   // beta^_1023[256]
        int   eb = 0, e_dn_save = 0;
        float sc_cm = 1.f;
        float dq0, dq1, dq2, dq3, dpb, dqs1, dqs2, dqs3;
        float c256, comb;

        // init prep for update u=0 (row 1023, slot 0)
        dq0 = dbr[0][0] + EPS_; dq1 = dbr[0][1] + EPS_;
        dq2 = dbr[0][2] + EPS_; dq3 = dbr[0][3] + EPS_;
        dpb = dpr[0] + EPS_;
        dqs1 = sk1 * dq1; dqs2 = sk2 * dq2; dqs3 = sk3 * dq3;
        {
            const float gcomb = fmaf(sk0 * dq0, b1, dpb * b0);  // = 0
            c256 = dpb * b256;
            const float gsh = __shfl_down_sync(FULL, gcomb, 1);
            comb = (lane == 31) ? c256 : gsh * sc_cm;
        }

        // u = 0..455 (refills load rows 1015 down to 560)
        for (int ub = 0; ub < 456; ub += 8) { BBLK8(ub) }
        // u = 456..463 (no refills; ring holds rows 560..567)
        BBLK8_LAST(456)

        // publish beta^_559 (per-lane scale 2^eb)
        sb_b[lane * 9 + 0] = b0; sb_b[lane * 9 + 1] = b1;
        sb_b[lane * 9 + 2] = b2; sb_b[lane * 9 + 3] = b3;
        sb_b[lane * 9 + 4] = b4; sb_b[lane * 9 + 5] = b5;
        sb_b[lane * 9 + 6] = b6; sb_b[lane * 9 + 7] = b7;
        sb_b[lane * 9 + 8] = b256;
        sb_e[lane] = eb;
    } else if (wrp == 2) {
        float zs = zhalf(row + (size_t)(lane >> 3) * C_ + (size_t)(lane & 7) * 16);
        if (lane == 0) s_z[0] = zs;
    } else {
        float zs = zhalf(row + (size_t)512 * C_
                         + (size_t)(lane >> 3) * C_ + (size_t)(lane & 7) * 16);
        if (lane == 0) s_z[1] = zs;
    }

    __syncthreads();

    // ---------------- combine on warp 0 (alpha_559 . beta^_559) -----------
    if (wrp == 0) {
        const float* bb = sb_b + lane * 9;
        float dot = a0 * bb[0] + a1 * bb[1] + a2 * bb[2] + a3 * bb[3]
                  + a4 * bb[4] + a5 * bb[5] + a6 * bb[6] + a7 * bb[7];
        if (lane == 31) dot = fmaf(a256, bb[8], dot);
        const int el = e + sb_e[lane];
        int elm = (dot > 0.f) ? el : -1000000;
        elm = max(elm, __shfl_xor_sync(FULL, elm, 1));
        elm = max(elm, __shfl_xor_sync(FULL, elm, 2));
        elm = max(elm, __shfl_xor_sync(FULL, elm, 4));
        elm = max(elm, __shfl_xor_sync(FULL, elm, 8));
        elm = max(elm, __shfl_xor_sync(FULL, elm, 16));
        const int d = el - elm + 127;
        const float sc = (dot > 0.f && d >= 1) ? __int_as_float(d << 23) : 0.f;
        float s = dot * sc;
        s += __shfl_xor_sync(FULL, s, 1);
        s += __shfl_xor_sync(FULL, s, 2);
        s += __shfl_xor_sync(FULL, s, 4);
        s += __shfl_xor_sync(FULL, s, 8);
        s += __shfl_xor_sync(FULL, s, 16);
        if (lane == 0) {
            float ll = __logf(s) + (float)elm * LN2 - (s_z[0] + s_z[1]);
            out[b] = -ll;
        }
    }
}

extern "C" void kernel_launch(void* const* d_in, const int* in_sizes, int n_in,
                              void* d_out, int out_size)
{
    const int* y_true;
    const float* y_pred;
    if (in_sizes[0] == 128 * L_) {            // y_true: [B,L] int32
        y_true = (const int*)d_in[0];
        y_pred = (const float*)d_in[1];
    } else {
        y_true = (const int*)d_in[1];
        y_pred = (const float*)d_in[0];
    }
    const int B = out_size;                    // [B,1] float32
    ctc_fb3_kernel<<<B, 128>>>(y_true, y_pred, (float*)d_out);
}